// round 4
// baseline (speedup 1.0000x reference)
#include <cuda_runtime.h>
#include <math.h>

#define FDIM 512
#define HDIM 256
#define LDIM 40
#define GEMB_DIM 1144   // 2*FDIM + 3*LDIM

// ---------------- side-stream resources (host-side handles; NOT device mem) ----
static cudaStream_t g_s2 = 0;
static cudaEvent_t  g_ev_fork = 0, g_ev_join = 0;
namespace {
struct SideStreamInit {
    SideStreamInit() {
        cudaStreamCreateWithFlags(&g_s2, cudaStreamNonBlocking);
        cudaEventCreateWithFlags(&g_ev_fork, cudaEventDisableTiming);
        cudaEventCreateWithFlags(&g_ev_join, cudaEventDisableTiming);
    }
};
static SideStreamInit g_side_init;
}

// ---------------- bulk copy: streaming (evict-first) LDG.128/STG.128 ----------------
__device__ __forceinline__ float4 ldg_cs(const float4* p) {
    float4 v;
    asm volatile("ld.global.cs.v4.f32 {%0,%1,%2,%3}, [%4];"
                 : "=f"(v.x), "=f"(v.y), "=f"(v.z), "=f"(v.w) : "l"(p));
    return v;
}
__device__ __forceinline__ void stg_cs(float4* p, float4 v) {
    asm volatile("st.global.cs.v4.f32 [%0], {%1,%2,%3,%4};"
                 :: "l"(p), "f"(v.x), "f"(v.y), "f"(v.z), "f"(v.w) : "memory");
}

__global__ void __launch_bounds__(512, 2)
k_copy(const float4* __restrict__ src, float4* __restrict__ dst, long n4) {
    long stride = (long)gridDim.x * blockDim.x;
    long i = (long)blockIdx.x * blockDim.x + threadIdx.x;
    for (; i + 3 * stride < n4; i += 4 * stride) {
        float4 a = ldg_cs(src + i);
        float4 b = ldg_cs(src + i + stride);
        float4 c = ldg_cs(src + i + 2 * stride);
        float4 d = ldg_cs(src + i + 3 * stride);
        stg_cs(dst + i, a);
        stg_cs(dst + i + stride, b);
        stg_cs(dst + i + 2 * stride, c);
        stg_cs(dst + i + 3 * stride, d);
    }
    for (; i < n4; i += stride) stg_cs(dst + i, ldg_cs(src + i));
}

// ---------------- fused chain: everything in ONE block of 512 threads ----------------
__global__ void __launch_bounds__(512, 1)
k_chain(const int* __restrict__ tgt, const int* __restrict__ sgn, int SG,
        const float* __restrict__ feat, const float* __restrict__ node_emb,
        const float* __restrict__ wlabel, const float* __restrict__ wsec,
        const float* __restrict__ w1, const float* __restrict__ w2,
        const float* __restrict__ W1, const float* __restrict__ b1,
        const float* __restrict__ W2, const float* __restrict__ b2,
        const float* __restrict__ W3, const float* __restrict__ b3,
        const int* __restrict__ feat_num_ptr, int budget_fallback,
        float* __restrict__ out, long nrowsF, int has_tail) {
    __shared__ float s_red[512];
    __shared__ float s_gemb[GEMB_DIM];
    __shared__ float s_tmp[HDIM];
    __shared__ float s_h1[128];
    __shared__ float s_h2[FDIM];
    __shared__ float s_logit[FDIM];

    int tid  = threadIdx.x;
    int lane = tid & 31;
    int t    = tgt[0];

    // ---- S1: sub_graph_emb = mean(node_emb[sgn]) ; also node_emb[target] ----
    {
        float acc = 0.f;
        #pragma unroll 4
        for (int r = 0; r < SG; ++r) {
            int row = __ldg(&sgn[r]);
            acc += __ldg(&node_emb[(size_t)row * FDIM + tid]);
        }
        s_gemb[tid] = acc / (float)SG;
        s_gemb[FDIM + tid] = __ldg(&node_emb[(size_t)t * FDIM + tid]);
    }

    // ---- S2: tmp = relu(feat[t] @ w1)  (256 outs, K=512 split 2) ----
    {
        int o = tid & 255, part = tid >> 8;          // part 0..1
        const float* fr = feat + (size_t)t * FDIM;
        float acc = 0.f;
        int k0 = part * 256;
        #pragma unroll 8
        for (int k = k0; k < k0 + 256; ++k)
            acc += __ldg(&fr[k]) * __ldg(&w1[(size_t)k * HDIM + o]);
        s_red[tid] = acc;
    }
    __syncthreads();
    if (tid < HDIM) s_tmp[tid] = fmaxf(s_red[tid] + s_red[tid + 256], 0.f);
    __syncthreads();

    // ---- S3: tarfeat = tmp @ w2  (40 outs, K=256 split 8) ----
    if (tid < 320) {
        int o = tid % 40, part = tid / 40;           // part 0..7
        float acc = 0.f;
        int k0 = part * 32;
        #pragma unroll
        for (int k = k0; k < k0 + 32; ++k)
            acc += s_tmp[k] * __ldg(&w2[k * LDIM + o]);
        s_red[tid] = acc;
    }
    __syncthreads();
    if (tid < LDIM) {
        float acc = 0.f;
        #pragma unroll
        for (int p = 0; p < 8; ++p) acc += s_red[tid + 40 * p];
        s_gemb[2 * FDIM + tid]            = acc;
        s_gemb[2 * FDIM + LDIM + tid]     = wlabel[tid];
        s_gemb[2 * FDIM + 2 * LDIM + tid] = wsec[tid];
    }
    __syncthreads();

    // ---- S4: h1 = leaky(gemb @ W1 + b1)  (128 outs, K=1144 split 4x286) ----
    {
        int o = tid & 127, part = tid >> 7;          // part 0..3
        float acc = 0.f;
        int k0 = part * 286;
        #pragma unroll 11
        for (int k = k0; k < k0 + 286; ++k)
            acc += s_gemb[k] * __ldg(&W1[(size_t)k * 128 + o]);
        s_red[tid] = acc;
    }
    __syncthreads();
    if (tid < 128) {
        float v = s_red[tid] + s_red[tid + 128] + s_red[tid + 256] + s_red[tid + 384] + b1[tid];
        s_h1[tid] = (v > 0.f) ? v : 0.01f * v;
    }
    __syncthreads();

    // ---- S5: h2 = leaky(h1 @ W2 + b2)  (512 outs, K=128) ----
    {
        float acc = 0.f;
        #pragma unroll 8
        for (int k = 0; k < 128; ++k)
            acc += s_h1[k] * __ldg(&W2[(size_t)k * FDIM + tid]);
        float v = acc + b2[tid];
        s_h2[tid] = (v > 0.f) ? v : 0.01f * v;
    }
    __syncthreads();

    // ---- S6: logits = h2 @ W3 + b3  (512 outs, K=512) ----
    {
        float acc = 0.f;
        #pragma unroll 8
        for (int k = 0; k < 512; ++k)
            acc += s_h2[k] * __ldg(&W3[(size_t)k * FDIM + tid]);
        s_logit[tid] = acc + b3[tid];
    }
    __syncthreads();

    // ---- S7: gumbel_topk (warp 0 only; all shuffle, no barriers) ----
    if (tid < 32) {
        int budget = feat_num_ptr ? feat_num_ptr[0] : budget_fallback;
        if (budget < 1) budget = 1;
        if (budget > FDIM) budget = FDIM;

        float lv[16], inj[16];
        unsigned mask16 = 0;
        #pragma unroll
        for (int j = 0; j < 16; ++j) { lv[j] = s_logit[j * 32 + lane]; inj[j] = 0.f; }

        for (int it = 0; it < budget; ++it) {
            // local argmax over unmasked (ascending j => strict '>' keeps lowest idx)
            float bv = -INFINITY; int bi = 0x7fffffff;
            #pragma unroll
            for (int j = 0; j < 16; ++j) {
                if (!((mask16 >> j) & 1u)) {
                    float v = lv[j];
                    if (v > bv) { bv = v; bi = j * 32 + lane; }
                }
            }
            // warp argmax, lowest-index tiebreak
            #pragma unroll
            for (int off = 16; off; off >>= 1) {
                float ov = __shfl_down_sync(0xffffffffu, bv, off);
                int   oi = __shfl_down_sync(0xffffffffu, bi, off);
                if (ov > bv || (ov == bv && oi < bi)) { bv = ov; bi = oi; }
            }
            bv = __shfl_sync(0xffffffffu, bv, 0);
            bi = __shfl_sync(0xffffffffu, bi, 0);

            // softmax over unmasked (masked entries would underflow to 0 anyway)
            float e[16], ls = 0.f;
            #pragma unroll
            for (int j = 0; j < 16; ++j) {
                e[j] = ((mask16 >> j) & 1u) ? 0.f : __expf((lv[j] - bv) * 1000.0f);
                ls += e[j];
            }
            #pragma unroll
            for (int off = 16; off; off >>= 1)
                ls += __shfl_down_sync(0xffffffffu, ls, off);
            float total = __shfl_sync(0xffffffffu, ls, 0);

            #pragma unroll
            for (int j = 0; j < 16; ++j) inj[j] += e[j] / total;

            if ((bi & 31) == lane) mask16 |= 1u << (bi >> 5);
        }

        #pragma unroll
        for (int j = 0; j < 16; ++j) {
            long idx = nrowsF + j * 32 + lane;
            out[idx] = inj[j];                        // new_feat row N
            if (has_tail) out[idx + FDIM] = inj[j];   // separate inj_feat output
        }
    }
}

// ---------------- launch ----------------
extern "C" void kernel_launch(void* const* d_in, const int* in_sizes, int n_in,
                              void* d_out, int out_size) {
    const int*   target   = (const int*)d_in[0];
    const int*   sgn      = (const int*)d_in[1];
    const float* feat     = (const float*)d_in[2];
    const float* node_emb = (const float*)d_in[3];
    const float* wlabel   = (const float*)d_in[4];
    const float* wsec     = (const float*)d_in[5];
    const float* w1       = (const float*)d_in[6];
    const float* w2       = (const float*)d_in[7];
    const float* W1       = (const float*)d_in[8];
    const float* b1       = (const float*)d_in[9];
    const float* W2       = (const float*)d_in[10];
    const float* b2       = (const float*)d_in[11];
    const float* W3       = (const float*)d_in[12];
    const float* b3       = (const float*)d_in[13];
    const int*   feat_num = (n_in > 14) ? (const int*)d_in[14] : (const int*)0;

    int  SG = in_sizes[1];
    long NF = (long)in_sizes[2];           // N * F
    float* out = (float*)d_out;
    int has_tail = ((long)out_size >= NF + 2L * FDIM) ? 1 : 0;

    bool fork = (g_s2 != 0) && (g_ev_fork != 0) && (g_ev_join != 0);
    cudaStream_t sc = fork ? g_s2 : (cudaStream_t)0;

    if (fork) {
        cudaEventRecord(g_ev_fork, 0);
        cudaStreamWaitEvent(g_s2, g_ev_fork, 0);
    }

    // Bulk: new_feat[0:N] = feat via streaming SM copy
    long n4 = NF / 4;                      // NF is a multiple of 512
    k_copy<<<1184, 512>>>((const float4*)feat, (float4*)out, n4);

    // Entire small chain fused into one single-block kernel, overlapped with copy
    k_chain<<<1, 512, 0, sc>>>(target, sgn, SG, feat, node_emb, wlabel, wsec,
                               w1, w2, W1, b1, W2, b2, W3, b3,
                               feat_num, 50, out, NF, has_tail);

    if (fork) {
        cudaEventRecord(g_ev_join, g_s2);
        cudaStreamWaitEvent(0, g_ev_join, 0);
    }
}

// round 5
// speedup vs baseline: 1.9279x; 1.9279x over previous
#include <cuda_runtime.h>
#include <math.h>

#define FDIM 512
#define HDIM 256
#define LDIM 40
#define GEMB_DIM 1144   // 2*FDIM + 3*LDIM

// ---------------- scratch (device globals; no allocation) ----------------
__device__ float g_part_sge[16][FDIM];   // subgraph mean partials
__device__ float g_part_tmp[8][HDIM];    // feat[t]@weight1 partials (pre-relu)
__device__ float g_gemb[GEMB_DIM];       // assembled graph embedding
__device__ float g_part_h1[8][128];      // gemb@W1 partials (pre-bias/act)
__device__ float g_part_h2[8][FDIM];     // h1@W2 partials
__device__ float g_part_add[16][FDIM];   // h2@W3 partials

// ---------------- side-stream resources (host-side handles; NOT device mem) ----
static cudaStream_t g_s2 = 0;
static cudaEvent_t  g_ev_fork = 0, g_ev_join = 0;
namespace {
struct SideStreamInit {
    SideStreamInit() {
        cudaStreamCreateWithFlags(&g_s2, cudaStreamNonBlocking);
        cudaEventCreateWithFlags(&g_ev_fork, cudaEventDisableTiming);
        cudaEventCreateWithFlags(&g_ev_join, cudaEventDisableTiming);
    }
};
static SideStreamInit g_side_init;
}

// ---------------- bulk copy: streaming (evict-first) LDG.128/STG.128 ----------------
__device__ __forceinline__ float4 ldg_cs(const float4* p) {
    float4 v;
    asm volatile("ld.global.cs.v4.f32 {%0,%1,%2,%3}, [%4];"
                 : "=f"(v.x), "=f"(v.y), "=f"(v.z), "=f"(v.w) : "l"(p));
    return v;
}
__device__ __forceinline__ void stg_cs(float4* p, float4 v) {
    asm volatile("st.global.cs.v4.f32 [%0], {%1,%2,%3,%4};"
                 :: "l"(p), "f"(v.x), "f"(v.y), "f"(v.z), "f"(v.w) : "memory");
}

__global__ void __launch_bounds__(256, 4)
k_copy(const float4* __restrict__ src, float4* __restrict__ dst, long n4) {
    long stride = (long)gridDim.x * blockDim.x;
    long i = (long)blockIdx.x * blockDim.x + threadIdx.x;
    for (; i + 3 * stride < n4; i += 4 * stride) {
        float4 a = ldg_cs(src + i);
        float4 b = ldg_cs(src + i + stride);
        float4 c = ldg_cs(src + i + 2 * stride);
        float4 d = ldg_cs(src + i + 3 * stride);
        stg_cs(dst + i, a);
        stg_cs(dst + i + stride, b);
        stg_cs(dst + i + 2 * stride, c);
        stg_cs(dst + i + 3 * stride, d);
    }
    for (; i < n4; i += stride) stg_cs(dst + i, ldg_cs(src + i));
}

// ---------------- stage A: subgraph partial sums + feat[t]@weight1 ----------------
__global__ void k_stageA(const int* __restrict__ tgt, const int* __restrict__ sgn, int SG,
                         const float* __restrict__ node_emb, const float* __restrict__ feat,
                         const float* __restrict__ w1) {
    int b = blockIdx.x, tid = threadIdx.x;
    if (b < 16) {
        int chunk = (SG + 15) >> 4;
        int r0 = b * chunk;
        int r1 = r0 + chunk; if (r1 > SG) r1 = SG;
        float acc = 0.f;
        for (int r = r0; r < r1; ++r) {
            int row = __ldg(&sgn[r]);
            acc += __ldg(&node_emb[(size_t)row * FDIM + tid]);
        }
        g_part_sge[b][tid] = acc;
    } else {
        int bb = b - 16;
        if (tid < HDIM) {
            int t = tgt[0];
            const float* fr = feat + (size_t)t * FDIM;
            float acc = 0.f;
            int k0 = bb * 64;
            #pragma unroll 8
            for (int k = k0; k < k0 + 64; ++k)
                acc += __ldg(&fr[k]) * __ldg(&w1[(size_t)k * HDIM + tid]);
            g_part_tmp[bb][tid] = acc;
        }
    }
}

// ---------------- stage B: assemble graph_emb [1144] ----------------
__global__ void k_assemble(const int* __restrict__ tgt, int SG,
                           const float* __restrict__ node_emb,
                           const float* __restrict__ w2,
                           const float* __restrict__ wlabel,
                           const float* __restrict__ wsec) {
    __shared__ float s_tmp[HDIM];
    int tid = threadIdx.x;
    if (tid < HDIM) {
        float s = 0.f;
        #pragma unroll
        for (int p = 0; p < 8; ++p) s += g_part_tmp[p][tid];
        s_tmp[tid] = fmaxf(s, 0.f);     // relu
    }
    float s = 0.f;
    #pragma unroll
    for (int p = 0; p < 16; ++p) s += g_part_sge[p][tid];
    g_gemb[tid] = s / (float)SG;
    int t = tgt[0];
    g_gemb[FDIM + tid] = __ldg(&node_emb[(size_t)t * FDIM + tid]);
    __syncthreads();
    if (tid < LDIM) {
        float acc = 0.f;
        #pragma unroll 8
        for (int h = 0; h < HDIM; ++h)
            acc += s_tmp[h] * __ldg(&w2[h * LDIM + tid]);
        g_gemb[2 * FDIM + tid]            = acc;          // tarfeat_emb
        g_gemb[2 * FDIM + LDIM + tid]     = wlabel[tid];
        g_gemb[2 * FDIM + 2 * LDIM + tid] = wsec[tid];
    }
}

// ---------------- stage C: h1 = gemb @ W1[1144,128]  (grid 8 x 128, K-chunk 143) ----------------
__global__ void k_h1(const float* __restrict__ W1) {
    int b = blockIdx.x, tid = threadIdx.x;
    float acc = 0.f;
    int k0 = b * 143;
    #pragma unroll 11
    for (int k = k0; k < k0 + 143; ++k)
        acc += g_gemb[k] * __ldg(&W1[(size_t)k * 128 + tid]);
    g_part_h1[b][tid] = acc;
}

// ---------------- stage D: h2 = leaky(h1+b1) @ W2[128,512]  (grid 8 x 512, K-chunk 16) ----------------
__global__ void k_h2(const float* __restrict__ b1, const float* __restrict__ W2) {
    __shared__ float s_h[16];
    int b = blockIdx.x, tid = threadIdx.x;
    int k0 = b * 16;
    if (tid < 16) {
        float v = 0.f;
        #pragma unroll
        for (int p = 0; p < 8; ++p) v += g_part_h1[p][k0 + tid];
        v += b1[k0 + tid];
        s_h[tid] = (v > 0.f) ? v : 0.01f * v;   // leaky relu
    }
    __syncthreads();
    float acc = 0.f;
    #pragma unroll
    for (int j = 0; j < 16; ++j)
        acc += s_h[j] * __ldg(&W2[(size_t)(k0 + j) * FDIM + tid]);
    g_part_h2[b][tid] = acc;
}

// ---------------- stage E: add = leaky(h2+b2) @ W3[512,512]  (grid 16 x 512, K-chunk 32) ----------------
__global__ void k_add(const float* __restrict__ b2, const float* __restrict__ W3) {
    __shared__ float s_h[32];
    int b = blockIdx.x, tid = threadIdx.x;
    int k0 = b * 32;
    if (tid < 32) {
        float v = 0.f;
        #pragma unroll
        for (int p = 0; p < 8; ++p) v += g_part_h2[p][k0 + tid];
        v += b2[k0 + tid];
        s_h[tid] = (v > 0.f) ? v : 0.01f * v;
    }
    __syncthreads();
    float acc = 0.f;
    #pragma unroll
    for (int j = 0; j < 32; ++j)
        acc += s_h[j] * __ldg(&W3[(size_t)(k0 + j) * FDIM + tid]);
    g_part_add[b][tid] = acc;
}

// ---------------- stage F: gumbel_topk + write inj_feat ----------------
__global__ void k_gumbel(const float* __restrict__ b3, const int* __restrict__ feat_num_ptr,
                         int budget_fallback, float* __restrict__ out,
                         long nrowsF, int has_tail) {
    int tid = threadIdx.x;
    float logit = 0.f;
    #pragma unroll
    for (int p = 0; p < 16; ++p) logit += g_part_add[p][tid];
    logit += b3[tid];

    __shared__ float s_wv[16];
    __shared__ int   s_wi[16];
    __shared__ float s_ws[16];
    __shared__ float s_bestv;
    __shared__ int   s_besti;
    __shared__ float s_sum;

    int lane = tid & 31, wid = tid >> 5;
    bool masked = false;
    float inj = 0.f;

    int budget = feat_num_ptr ? feat_num_ptr[0] : budget_fallback;
    if (budget < 1) budget = 1;
    if (budget > FDIM) budget = FDIM;

    for (int it = 0; it < budget; ++it) {
        // block argmax (lowest index wins ties, like jnp.argmax)
        float v = masked ? -INFINITY : logit;
        int bi = tid;
        #pragma unroll
        for (int off = 16; off; off >>= 1) {
            float ov = __shfl_down_sync(0xffffffffu, v, off);
            int   oi = __shfl_down_sync(0xffffffffu, bi, off);
            if (ov > v || (ov == v && oi < bi)) { v = ov; bi = oi; }
        }
        if (lane == 0) { s_wv[wid] = v; s_wi[wid] = bi; }
        __syncthreads();
        if (wid == 0) {
            float v2 = (lane < 16) ? s_wv[lane] : -INFINITY;
            int   i2 = (lane < 16) ? s_wi[lane] : 0x7fffffff;
            #pragma unroll
            for (int off = 8; off; off >>= 1) {
                float ov = __shfl_down_sync(0xffffffffu, v2, off);
                int   oi = __shfl_down_sync(0xffffffffu, i2, off);
                if (ov > v2 || (ov == v2 && oi < i2)) { v2 = ov; i2 = oi; }
            }
            if (lane == 0) { s_bestv = v2; s_besti = i2; }
        }
        __syncthreads();
        float m = s_bestv;
        int  mi = s_besti;

        // softmax over unmasked entries (masked underflow to exact 0)
        float e = masked ? 0.f : __expf((logit - m) * 1000.0f);
        float s = e;
        #pragma unroll
        for (int off = 16; off; off >>= 1) s += __shfl_down_sync(0xffffffffu, s, off);
        if (lane == 0) s_ws[wid] = s;
        __syncthreads();
        if (wid == 0) {
            float s2 = (lane < 16) ? s_ws[lane] : 0.f;
            #pragma unroll
            for (int off = 8; off; off >>= 1) s2 += __shfl_down_sync(0xffffffffu, s2, off);
            if (lane == 0) s_sum = s2;
        }
        __syncthreads();
        inj += e / s_sum;
        if (tid == mi) masked = true;
        __syncthreads();
    }

    out[nrowsF + tid] = inj;                       // new_feat row N
    if (has_tail) out[nrowsF + FDIM + tid] = inj;  // separate inj_feat output
}

// ---------------- launch ----------------
extern "C" void kernel_launch(void* const* d_in, const int* in_sizes, int n_in,
                              void* d_out, int out_size) {
    const int*   target   = (const int*)d_in[0];
    const int*   sgn      = (const int*)d_in[1];
    const float* feat     = (const float*)d_in[2];
    const float* node_emb = (const float*)d_in[3];
    const float* wlabel   = (const float*)d_in[4];
    const float* wsec     = (const float*)d_in[5];
    const float* w1       = (const float*)d_in[6];
    const float* w2       = (const float*)d_in[7];
    const float* W1       = (const float*)d_in[8];
    const float* b1       = (const float*)d_in[9];
    const float* W2       = (const float*)d_in[10];
    const float* b2       = (const float*)d_in[11];
    const float* W3       = (const float*)d_in[12];
    const float* b3       = (const float*)d_in[13];
    const int*   feat_num = (n_in > 14) ? (const int*)d_in[14] : (const int*)0;

    int  SG = in_sizes[1];
    long NF = (long)in_sizes[2];           // N * F
    float* out = (float*)d_out;
    int has_tail = ((long)out_size >= NF + 2L * FDIM) ? 1 : 0;

    bool fork = (g_s2 != 0) && (g_ev_fork != 0) && (g_ev_join != 0);
    cudaStream_t sc = fork ? g_s2 : (cudaStream_t)0;   // chain stream

    if (fork) {
        cudaEventRecord(g_ev_fork, 0);
        cudaStreamWaitEvent(g_s2, g_ev_fork, 0);
    }

    // Bulk: new_feat[0:N] = feat via streaming (evict-first) SM copy
    long n4 = NF / 4;                      // NF is a multiple of 512
    k_copy<<<2368, 256>>>((const float4*)feat, (float4*)out, n4);

    // Tiny serial chain (overlapped with the copy; writes only scratch + out tail)
    k_stageA  <<<24, 512, 0, sc>>>(target, sgn, SG, node_emb, feat, w1);
    k_assemble<<<1, 512, 0, sc>>>(target, SG, node_emb, w2, wlabel, wsec);
    k_h1      <<<8, 128, 0, sc>>>(W1);
    k_h2      <<<8, 512, 0, sc>>>(b1, W2);
    k_add     <<<16, 512, 0, sc>>>(b2, W3);
    k_gumbel  <<<1, 512, 0, sc>>>(b3, feat_num, 50, out, NF, has_tail);

    if (fork) {
        cudaEventRecord(g_ev_join, g_s2);
        cudaStreamWaitEvent(0, g_ev_join, 0);
    }
}